// round 15
// baseline (speedup 1.0000x reference)
#include <cuda_runtime.h>
#include <cuda_fp16.h>
#include <stdint.h>
#include <math.h>

#define M_TOTAL 8192
#define D 768
#define NSTATE 16

// Main GEMM tiling (R11-proven shape)
#define BM 128
#define BN 64
#define BK 64
#define NSTG 3
#define KTILES 12                 // single fp16 term: 768/64
#define ASTAGE (BM * BK * 2)      // 16384 B
#define BSTAGE (BN * BK * 2)      // 8192 B
#define STAGE_BYTES (ASTAGE + BSTAGE)   // 24576 B
#define GEMM_SMEM (NSTG * STAGE_BYTES)  // 73728 B -> 3 CTAs/SM

// s-GEMM tiling (128 rows x 32 cols, K=768 x 2 terms)
#define SBM 128
#define SBN 32
#define S_NSTG 3
#define S_ASTG (SBM * BK * 2)     // 16384 B
#define S_BSTG (SBN * BK * 2)     // 4096 B
#define S_STAGE (S_ASTG + S_BSTG) // 20480 B
#define S_SMEM (S_NSTG * S_STAGE) // 61440 B
#define S_KTILES 24               // 2 terms * 12

// ---------------- device scratch (no allocs allowed) ----------------
__device__ __align__(16) __half g_x_h[M_TOTAL * D];     // x rounded to fp16
__device__ __align__(16) __half g_wt_h[D * D];          // W1^T fp16: [n][k]
__device__ __align__(16) __half g_w23_h[32 * D];        // [W2|W3]^T hi: [n][k]
__device__ __align__(16) __half g_w23_l[32 * D];        // [W2|W3]^T residual
__device__ float g_s[M_TOTAL];

// ---------------- helpers ----------------
__device__ __forceinline__ uint32_t smem_u32(const void* p) {
    uint32_t a;
    asm("{ .reg .u64 t; cvta.to.shared.u64 t, %1; cvt.u32.u64 %0, t; }"
        : "=r"(a) : "l"(p));
    return a;
}
#define SW128(o) ((o) ^ (((o) >> 3) & 0x70))

__device__ __forceinline__ void cp_async16(uint32_t dst, const void* src) {
    asm volatile("cp.async.cg.shared.global [%0], [%1], 16;" :: "r"(dst), "l"(src));
}

__device__ __forceinline__ void ldmatrix_x4(uint32_t& r0, uint32_t& r1,
                                            uint32_t& r2, uint32_t& r3,
                                            uint32_t addr) {
    asm volatile("ldmatrix.sync.aligned.m8n8.x4.shared.b16 {%0,%1,%2,%3}, [%4];"
                 : "=r"(r0), "=r"(r1), "=r"(r2), "=r"(r3) : "r"(addr));
}

__device__ __forceinline__ void mma_f16(float* c,
                                        uint32_t a0, uint32_t a1, uint32_t a2, uint32_t a3,
                                        uint32_t b0, uint32_t b1) {
    asm volatile("mma.sync.aligned.m16n8k16.row.col.f32.f16.f16.f32 "
                 "{%0,%1,%2,%3}, {%4,%5,%6,%7}, {%8,%9}, {%0,%1,%2,%3};"
                 : "+f"(c[0]), "+f"(c[1]), "+f"(c[2]), "+f"(c[3])
                 : "r"(a0), "r"(a1), "r"(a2), "r"(a3), "r"(b0), "r"(b1));
}

__device__ __forceinline__ float softplus_f(float z) {
    if (z > 20.f) return z;
    return log1pf(__expf(z));
}

// ---------------------------------------------------------------------------
// k_conv: pure streaming conversions.
//   blocks [0, 1536):        x -> fp16 (4 float4s per thread)
//   blocks [1536, 2112):     W1 transpose + fp16 (32x32 tile each)
//   blocks [2112, 2136):     [W2|W3]^T fp16 hi/lo (32 k-rows each)
// ---------------------------------------------------------------------------
#define CONV_XBLK ((M_TOTAL * D / 4) / (256 * 4))   // 1536
#define WT_TILES  ((D / 32) * (D / 32))             // 576
#define W23_BLKS  (D / 32)                          // 24

__global__ void __launch_bounds__(256) k_conv(
    const float* __restrict__ x,
    const float* __restrict__ W1,
    const float* __restrict__ W2,
    const float* __restrict__ W3)
{
    const int tid = threadIdx.x;
    const int b = blockIdx.x;

    if (b < CONV_XBLK) {
#pragma unroll
        for (int p = 0; p < 4; p++) {
            int i = b * 1024 + p * 256 + tid;
            float4 v = *((const float4*)x + i);
            __half2 h0 = __floats2half2_rn(v.x, v.y);
            __half2 h1 = __floats2half2_rn(v.z, v.w);
            uint2 u;
            u.x = *(uint32_t*)&h0;
            u.y = *(uint32_t*)&h1;
            *(uint2*)(g_x_h + 4 * (size_t)i) = u;
        }
        return;
    }
    if (b < CONV_XBLK + WT_TILES) {
        __shared__ float t[32][33];
        int tile = b - CONV_XBLK;
        int n0 = (tile % (D / 32)) * 32;
        int k0 = (tile / (D / 32)) * 32;
        int tx = tid & 31, ty = tid >> 5;
#pragma unroll
        for (int r = 0; r < 32; r += 8)
            t[ty + r][tx] = W1[(size_t)(k0 + ty + r) * D + n0 + tx];
        __syncthreads();
#pragma unroll
        for (int r = 0; r < 32; r += 8)
            g_wt_h[(size_t)(n0 + ty + r) * D + k0 + tx] =
                __float2half_rn(t[tx][ty + r]);
        return;
    }
    {
        // [W2|W3]^T hi/lo: 32 k-rows x 16 n x 2 matrices = 1024 elements
        int k0 = (b - CONV_XBLK - WT_TILES) * 32;
#pragma unroll
        for (int it = 0; it < 4; it++) {
            int idx = it * 256 + tid;        // 0..1023
            int mat = idx >> 9;              // 0: W2, 1: W3
            int rem = idx & 511;
            int r = rem >> 4;                // k offset 0..31
            int n = rem & 15;
            const float* src = mat ? W3 : W2;
            float v = src[(size_t)(k0 + r) * NSTATE + n];
            __half h = __float2half_rn(v);
            __half l = __float2half_rn(v - __half2float(h));
            size_t o = (size_t)(mat * 16 + n) * D + k0 + r;
            g_w23_h[o] = h;
            g_w23_l[o] = l;
        }
    }
}

// ---------------------------------------------------------------------------
// k_s_mma: G = x_h @ [W2|W3] (2-term hi/lo on W), then
// s[m] = dot(G[m,0:16]+b2, G[m,16:32]+b3) directly from the mma accumulators.
// 64 CTAs x 128 thr: CTA = 128 rows x 32 cols; 4 warps (32 rows each, mi=2).
// ---------------------------------------------------------------------------
__global__ void __launch_bounds__(128, 3) k_s_mma(
    const float* __restrict__ b2, const float* __restrict__ b3)
{
    extern __shared__ __align__(1024) char smem[];
    const uint32_t sbase = smem_u32(smem);
    const int tid = threadIdx.x;
    const int wid = tid >> 5, lane = tid & 31;
    const int row0 = blockIdx.x * SBM;

    uint32_t dstA[8], srcA[8], dstB[2], srcB[2];
#pragma unroll
    for (int c = 0; c < 8; c++) {
        int i = c * 128 + tid;
        int r = i >> 3, cw = i & 7;
        dstA[c] = SW128((uint32_t)(i * 16));
        srcA[c] = (uint32_t)(row0 + r) * (D * 2) + cw * 16;
    }
#pragma unroll
    for (int c = 0; c < 2; c++) {
        int i = c * 128 + tid;
        int r = i >> 3, cw = i & 7;
        dstB[c] = SW128((uint32_t)(i * 16));
        srcB[c] = (uint32_t)r * (D * 2) + cw * 16;
    }
    const char* const xh = (const char*)g_x_h;
    const char* const wh = (const char*)g_w23_h;
    const char* const wl = (const char*)g_w23_l;

    uint32_t Abase[2], Amask[2];
#pragma unroll
    for (int mi = 0; mi < 2; mi++) {
        int m = wid * 32 + (lane & 15) + mi * 16;
        Abase[mi] = (uint32_t)(m * 128);
        Amask[mi] = (uint32_t)((m << 4) & 0x70);
    }
    const uint32_t akb = (uint32_t)((lane >> 4) * 16);
    const uint32_t Bbase = (uint32_t)(lane * 128);
    const uint32_t Bmask = (uint32_t)((lane << 4) & 0x70);

    float acc[2][4][4];
#pragma unroll
    for (int mi = 0; mi < 2; mi++)
#pragma unroll
        for (int ni = 0; ni < 4; ni++)
#pragma unroll
            for (int q = 0; q < 4; q++) acc[mi][ni][q] = 0.f;

    auto load_tile = [&](int kt, uint32_t stage_off) {
        const char* Bb = (kt >= 12) ? wl : wh;
        int ktm = (kt >= 12) ? kt - 12 : kt;
        uint32_t k0b = (uint32_t)(ktm * (BK * 2));
        uint32_t sa = sbase + stage_off;
        uint32_t sb = sa + S_ASTG;
#pragma unroll
        for (int c = 0; c < 8; c++)
            cp_async16(sa + dstA[c], xh + srcA[c] + k0b);
#pragma unroll
        for (int c = 0; c < 2; c++)
            cp_async16(sb + dstB[c], Bb + srcB[c] + k0b);
        asm volatile("cp.async.commit_group;" ::: "memory");
    };

    load_tile(0, 0);
    load_tile(1, S_STAGE);

#pragma unroll 3
    for (int kt = 0; kt < S_KTILES; kt++) {
        const uint32_t soff = (uint32_t)(kt % S_NSTG) * S_STAGE;
        if (kt < S_KTILES - 1)
            asm volatile("cp.async.wait_group 1;" ::: "memory");
        else
            asm volatile("cp.async.wait_group 0;" ::: "memory");
        __syncthreads();

        const int nx = kt + 2;
        if (nx < S_KTILES) load_tile(nx, (uint32_t)(nx % S_NSTG) * S_STAGE);

        const uint32_t sa = sbase + soff;
        const uint32_t sb = sa + S_ASTG;
#pragma unroll
        for (int ks = 0; ks < 4; ks++) {
            const uint32_t kk = (uint32_t)(ks * 32);
            uint32_t b0[4], b1r[4];
            ldmatrix_x4(b0[0], b0[1], b0[2], b0[3],
                        sb + Bbase + ((kk) ^ Bmask));
            ldmatrix_x4(b1r[0], b1r[1], b1r[2], b1r[3],
                        sb + Bbase + ((kk + 16) ^ Bmask));
            uint32_t a[2][4];
#pragma unroll
            for (int mi = 0; mi < 2; mi++)
                ldmatrix_x4(a[mi][0], a[mi][1], a[mi][2], a[mi][3],
                            sa + Abase[mi] + ((kk + akb) ^ Amask[mi]));
#pragma unroll
            for (int mi = 0; mi < 2; mi++)
#pragma unroll
                for (int ni = 0; ni < 4; ni++)
                    mma_f16(acc[mi][ni],
                            a[mi][0], a[mi][1], a[mi][2], a[mi][3],
                            b0[ni], b1r[ni]);
        }
    }

    // s epilogue: cols 0-15 = B-proj, 16-31 = C-proj.
    const int nq = (lane & 3) * 2;
    const float b2a = __ldg(b2 + nq),     b2a1 = __ldg(b2 + nq + 1);
    const float b2b = __ldg(b2 + 8 + nq), b2b1 = __ldg(b2 + 8 + nq + 1);
    const float b3a = __ldg(b3 + nq),     b3a1 = __ldg(b3 + nq + 1);
    const float b3b = __ldg(b3 + 8 + nq), b3b1 = __ldg(b3 + 8 + nq + 1);
#pragma unroll
    for (int mi = 0; mi < 2; mi++) {
        float pa = (acc[mi][0][0] + b2a ) * (acc[mi][2][0] + b3a )
                 + (acc[mi][0][1] + b2a1) * (acc[mi][2][1] + b3a1)
                 + (acc[mi][1][0] + b2b ) * (acc[mi][3][0] + b3b )
                 + (acc[mi][1][1] + b2b1) * (acc[mi][3][1] + b3b1);
        float pb = (acc[mi][0][2] + b2a ) * (acc[mi][2][2] + b3a )
                 + (acc[mi][0][3] + b2a1) * (acc[mi][2][3] + b3a1)
                 + (acc[mi][1][2] + b2b ) * (acc[mi][3][2] + b3b )
                 + (acc[mi][1][3] + b2b1) * (acc[mi][3][3] + b3b1);
        pa += __shfl_xor_sync(0xffffffffu, pa, 1);
        pa += __shfl_xor_sync(0xffffffffu, pa, 2);
        pb += __shfl_xor_sync(0xffffffffu, pb, 1);
        pb += __shfl_xor_sync(0xffffffffu, pb, 2);
        if ((lane & 3) == 0) {
            int ma = row0 + wid * 32 + mi * 16 + (lane >> 2);
            g_s[ma] = pa;
            g_s[ma + 8] = pb;
        }
    }
}

// ---------------------------------------------------------------------------
// Main GEMM: single fp16 term (K=768), mma.sync m16n8k16, cp.async 3-stage.
// CTA 128x64, 8 warps (warp grid 4m x 2n, warp tile 32x32), 3 CTAs/SM.
// Fused epilogue: y = x_h * softplus(acc + b1) * s[m]   (x_h fp16, L2-hot).
// ---------------------------------------------------------------------------
__global__ void __launch_bounds__(256, 3) s6_mma_gemm(
    const float* __restrict__ b1, float* __restrict__ y)
{
    extern __shared__ __align__(1024) char smem[];
    const uint32_t sbase = smem_u32(smem);
    const int tid = threadIdx.x;
    const int wid = tid >> 5, lane = tid & 31;
    const int warp_m = wid & 3;        // 4 m-blocks of 32
    const int warp_n = wid >> 2;       // 2 n-blocks of 32
    const int row0 = blockIdx.y * BM;
    const int col0 = blockIdx.x * BN;

    uint32_t dstA[4], srcA[4], dstB[2], srcB[2];
#pragma unroll
    for (int c = 0; c < 4; c++) {
        int i = c * 256 + tid;
        int r = i >> 3, cw = i & 7;
        dstA[c] = SW128((uint32_t)(i * 16));
        srcA[c] = (uint32_t)(row0 + r) * (D * 2) + cw * 16;
    }
#pragma unroll
    for (int c = 0; c < 2; c++) {
        int i = c * 256 + tid;
        int r = i >> 3, cw = i & 7;
        dstB[c] = SW128((uint32_t)(i * 16));
        srcB[c] = (uint32_t)(col0 + r) * (D * 2) + cw * 16;
    }
    const char* const xh = (const char*)g_x_h;
    const char* const wh = (const char*)g_wt_h;

    uint32_t Abase[2], Amask[2];
#pragma unroll
    for (int mi = 0; mi < 2; mi++) {
        int m = warp_m * 32 + (lane & 15) + mi * 16;
        Abase[mi] = (uint32_t)(m * 128);
        Amask[mi] = (uint32_t)((m << 4) & 0x70);
    }
    const uint32_t akb = (uint32_t)((lane >> 4) * 16);
    const int bn = warp_n * 32 + lane;
    const uint32_t Bbase = (uint32_t)(bn * 128);
    const uint32_t Bmask = (uint32_t)((bn << 4) & 0x70);

    float acc[2][4][4];
#pragma unroll
    for (int mi = 0; mi < 2; mi++)
#pragma unroll
        for (int ni = 0; ni < 4; ni++)
#pragma unroll
            for (int q = 0; q < 4; q++) acc[mi][ni][q] = 0.f;

    auto load_tile = [&](int kt, uint32_t stage_off) {
        uint32_t k0b = (uint32_t)(kt * (BK * 2));
        uint32_t sa = sbase + stage_off;
        uint32_t sb = sa + ASTAGE;
#pragma unroll
        for (int c = 0; c < 4; c++)
            cp_async16(sa + dstA[c], xh + srcA[c] + k0b);
#pragma unroll
        for (int c = 0; c < 2; c++)
            cp_async16(sb + dstB[c], wh + srcB[c] + k0b);
        asm volatile("cp.async.commit_group;" ::: "memory");
    };

    load_tile(0, 0);
    load_tile(1, STAGE_BYTES);

#pragma unroll 3
    for (int kt = 0; kt < KTILES; kt++) {
        const uint32_t soff = (uint32_t)(kt % NSTG) * STAGE_BYTES;
        if (kt < KTILES - 1)
            asm volatile("cp.async.wait_group 1;" ::: "memory");
        else
            asm volatile("cp.async.wait_group 0;" ::: "memory");
        __syncthreads();

        const int nx = kt + 2;
        if (nx < KTILES) load_tile(nx, (uint32_t)(nx % NSTG) * STAGE_BYTES);

        const uint32_t sa = sbase + soff;
        const uint32_t sb = sa + ASTAGE;
#pragma unroll
        for (int ks = 0; ks < 4; ks++) {
            const uint32_t kk = (uint32_t)(ks * 32);
            uint32_t b0[4], b1r[4];
            ldmatrix_x4(b0[0], b0[1], b0[2], b0[3],
                        sb + Bbase + ((kk) ^ Bmask));
            ldmatrix_x4(b1r[0], b1r[1], b1r[2], b1r[3],
                        sb + Bbase + ((kk + 16) ^ Bmask));
            uint32_t a[2][4];
#pragma unroll
            for (int mi = 0; mi < 2; mi++)
                ldmatrix_x4(a[mi][0], a[mi][1], a[mi][2], a[mi][3],
                            sa + Abase[mi] + ((kk + akb) ^ Amask[mi]));
#pragma unroll
            for (int mi = 0; mi < 2; mi++)
#pragma unroll
                for (int ni = 0; ni < 4; ni++)
                    mma_f16(acc[mi][ni],
                            a[mi][0], a[mi][1], a[mi][2], a[mi][3],
                            b0[ni], b1r[ni]);
        }
    }

    // Fused epilogue (x read as fp16 from g_x_h — L2-hot, half the bytes)
    const int mbase = row0 + warp_m * 32;
    const int nbase = col0 + warp_n * 32;
#pragma unroll
    for (int mi = 0; mi < 2; mi++) {
        const int ma = mbase + mi * 16 + (lane >> 2);
        const int mb = ma + 8;
        const float s_a = g_s[ma];
        const float s_b = g_s[mb];
#pragma unroll
        for (int ni = 0; ni < 4; ni++) {
            const int n = nbase + ni * 8 + (lane & 3) * 2;
            float2 bb = *(const float2*)(b1 + n);
            __half2 xah = *(const __half2*)(g_x_h + (size_t)ma * D + n);
            __half2 xbh = *(const __half2*)(g_x_h + (size_t)mb * D + n);
            float2 xa = __half22float2(xah);
            float2 xb = __half22float2(xbh);
            float2 oa, ob;
            oa.x = xa.x * softplus_f(acc[mi][ni][0] + bb.x) * s_a;
            oa.y = xa.y * softplus_f(acc[mi][ni][1] + bb.y) * s_a;
            ob.x = xb.x * softplus_f(acc[mi][ni][2] + bb.x) * s_b;
            ob.y = xb.y * softplus_f(acc[mi][ni][3] + bb.y) * s_b;
            *(float2*)(y + (size_t)ma * D + n) = oa;
            *(float2*)(y + (size_t)mb * D + n) = ob;
        }
    }
}

// ---------------------------------------------------------------------------
// Launch. Inputs: x, W1, b1, W2, b2, W3, b3, A (A unused since h0 = 0).
// ---------------------------------------------------------------------------
extern "C" void kernel_launch(void* const* d_in, const int* in_sizes, int n_in,
                              void* d_out, int out_size)
{
    const float* x  = (const float*)d_in[0];
    const float* W1 = (const float*)d_in[1];
    const float* b1 = (const float*)d_in[2];
    const float* W2 = (const float*)d_in[3];
    const float* b2 = (const float*)d_in[4];
    const float* W3 = (const float*)d_in[5];
    const float* b3 = (const float*)d_in[6];
    float* y = (float*)d_out;

    static bool attr_set = false;
    if (!attr_set) {
        cudaFuncSetAttribute(s6_mma_gemm,
                             cudaFuncAttributeMaxDynamicSharedMemorySize, GEMM_SMEM);
        cudaFuncSetAttribute(k_s_mma,
                             cudaFuncAttributeMaxDynamicSharedMemorySize, S_SMEM);
        attr_set = true;
    }

    k_conv<<<CONV_XBLK + WT_TILES + W23_BLKS, 256>>>(x, W1, W2, W3);
    k_s_mma<<<M_TOTAL / SBM, 128, S_SMEM>>>(b2, b3);

    dim3 grid(D / BN, M_TOTAL / BM);   // (12, 64) = 768 CTAs
    s6_mma_gemm<<<grid, 256, GEMM_SMEM>>>(b1, y);
}

// round 16
// speedup vs baseline: 1.0075x; 1.0075x over previous
#include <cuda_runtime.h>
#include <cuda_fp16.h>
#include <stdint.h>
#include <math.h>

#define M_TOTAL 8192
#define D 768
#define NSTATE 16

// Main GEMM tiling (R11-proven shape)
#define BM 128
#define BN 64
#define BK 64
#define NSTG 3
#define KTILES 12                 // single fp16 term: 768/64
#define ASTAGE (BM * BK * 2)      // 16384 B
#define BSTAGE (BN * BK * 2)      // 8192 B
#define STAGE_BYTES (ASTAGE + BSTAGE)   // 24576 B
#define GEMM_SMEM (NSTG * STAGE_BYTES)  // 73728 B -> 3 CTAs/SM

// s-GEMM tiling (128 rows x 32 cols, K=768 x 2 terms)
#define SBM 128
#define SBN 32
#define S_NSTG 3
#define S_ASTG (SBM * BK * 2)     // 16384 B
#define S_BSTG (SBN * BK * 2)     // 4096 B
#define S_STAGE (S_ASTG + S_BSTG) // 20480 B
#define S_SMEM (S_NSTG * S_STAGE) // 61440 B
#define S_KTILES 24               // 2 terms * 12

// ---------------- device scratch (no allocs allowed) ----------------
__device__ __align__(16) __half g_x_h[M_TOTAL * D];     // x rounded to fp16
__device__ __align__(16) __half g_wt_h[D * D];          // W1^T fp16: [n][k]
__device__ __align__(16) __half g_w23_h[32 * D];        // [W2|W3]^T hi: [n][k]
__device__ __align__(16) __half g_w23_l[32 * D];        // [W2|W3]^T residual
__device__ float g_s[M_TOTAL];

// ---------------- helpers ----------------
__device__ __forceinline__ uint32_t smem_u32(const void* p) {
    uint32_t a;
    asm("{ .reg .u64 t; cvta.to.shared.u64 t, %1; cvt.u32.u64 %0, t; }"
        : "=r"(a) : "l"(p));
    return a;
}
#define SW128(o) ((o) ^ (((o) >> 3) & 0x70))

__device__ __forceinline__ void cp_async16(uint32_t dst, const void* src) {
    asm volatile("cp.async.cg.shared.global [%0], [%1], 16;" :: "r"(dst), "l"(src));
}

__device__ __forceinline__ void ldmatrix_x4(uint32_t& r0, uint32_t& r1,
                                            uint32_t& r2, uint32_t& r3,
                                            uint32_t addr) {
    asm volatile("ldmatrix.sync.aligned.m8n8.x4.shared.b16 {%0,%1,%2,%3}, [%4];"
                 : "=r"(r0), "=r"(r1), "=r"(r2), "=r"(r3) : "r"(addr));
}

__device__ __forceinline__ void mma_f16(float* c,
                                        uint32_t a0, uint32_t a1, uint32_t a2, uint32_t a3,
                                        uint32_t b0, uint32_t b1) {
    asm volatile("mma.sync.aligned.m16n8k16.row.col.f32.f16.f16.f32 "
                 "{%0,%1,%2,%3}, {%4,%5,%6,%7}, {%8,%9}, {%0,%1,%2,%3};"
                 : "+f"(c[0]), "+f"(c[1]), "+f"(c[2]), "+f"(c[3])
                 : "r"(a0), "r"(a1), "r"(a2), "r"(a3), "r"(b0), "r"(b1));
}

__device__ __forceinline__ float softplus_f(float z) {
    if (z > 20.f) return z;
    return log1pf(__expf(z));
}

// ---------------------------------------------------------------------------
// k_conv: pure streaming conversions.
//   blocks [0, 1536):        x -> fp16 (4 float4s per thread)
//   blocks [1536, 2112):     W1 transpose + fp16 (32x32 tile each)
//   blocks [2112, 2136):     [W2|W3]^T fp16 hi/lo (32 k-rows each)
// ---------------------------------------------------------------------------
#define CONV_XBLK ((M_TOTAL * D / 4) / (256 * 4))   // 1536
#define WT_TILES  ((D / 32) * (D / 32))             // 576
#define W23_BLKS  (D / 32)                          // 24

__global__ void __launch_bounds__(256) k_conv(
    const float* __restrict__ x,
    const float* __restrict__ W1,
    const float* __restrict__ W2,
    const float* __restrict__ W3)
{
    const int tid = threadIdx.x;
    const int b = blockIdx.x;

    if (b < CONV_XBLK) {
#pragma unroll
        for (int p = 0; p < 4; p++) {
            int i = b * 1024 + p * 256 + tid;
            float4 v = *((const float4*)x + i);
            __half2 h0 = __floats2half2_rn(v.x, v.y);
            __half2 h1 = __floats2half2_rn(v.z, v.w);
            uint2 u;
            u.x = *(uint32_t*)&h0;
            u.y = *(uint32_t*)&h1;
            *(uint2*)(g_x_h + 4 * (size_t)i) = u;
        }
        return;
    }
    if (b < CONV_XBLK + WT_TILES) {
        __shared__ float t[32][33];
        int tile = b - CONV_XBLK;
        int n0 = (tile % (D / 32)) * 32;
        int k0 = (tile / (D / 32)) * 32;
        int tx = tid & 31, ty = tid >> 5;
#pragma unroll
        for (int r = 0; r < 32; r += 8)
            t[ty + r][tx] = W1[(size_t)(k0 + ty + r) * D + n0 + tx];
        __syncthreads();
#pragma unroll
        for (int r = 0; r < 32; r += 8)
            g_wt_h[(size_t)(n0 + ty + r) * D + k0 + tx] =
                __float2half_rn(t[tx][ty + r]);
        return;
    }
    {
        // [W2|W3]^T hi/lo: 32 k-rows x 16 n x 2 matrices = 1024 elements
        int k0 = (b - CONV_XBLK - WT_TILES) * 32;
#pragma unroll
        for (int it = 0; it < 4; it++) {
            int idx = it * 256 + tid;        // 0..1023
            int mat = idx >> 9;              // 0: W2, 1: W3
            int rem = idx & 511;
            int r = rem >> 4;                // k offset 0..31
            int n = rem & 15;
            const float* src = mat ? W3 : W2;
            float v = src[(size_t)(k0 + r) * NSTATE + n];
            __half h = __float2half_rn(v);
            __half l = __float2half_rn(v - __half2float(h));
            size_t o = (size_t)(mat * 16 + n) * D + k0 + r;
            g_w23_h[o] = h;
            g_w23_l[o] = l;
        }
    }
}

// ---------------------------------------------------------------------------
// k_s_mma: G = x_h @ [W2|W3] (2-term hi/lo on W), then
// s[m] = dot(G[m,0:16]+b2, G[m,16:32]+b3) directly from the mma accumulators.
// 64 CTAs x 128 thr: CTA = 128 rows x 32 cols; 4 warps (32 rows each, mi=2).
// ---------------------------------------------------------------------------
__global__ void __launch_bounds__(128, 3) k_s_mma(
    const float* __restrict__ b2, const float* __restrict__ b3)
{
    extern __shared__ __align__(1024) char smem[];
    const uint32_t sbase = smem_u32(smem);
    const int tid = threadIdx.x;
    const int wid = tid >> 5, lane = tid & 31;
    const int row0 = blockIdx.x * SBM;

    uint32_t dstA[8], srcA[8], dstB[2], srcB[2];
#pragma unroll
    for (int c = 0; c < 8; c++) {
        int i = c * 128 + tid;
        int r = i >> 3, cw = i & 7;
        dstA[c] = SW128((uint32_t)(i * 16));
        srcA[c] = (uint32_t)(row0 + r) * (D * 2) + cw * 16;
    }
#pragma unroll
    for (int c = 0; c < 2; c++) {
        int i = c * 128 + tid;
        int r = i >> 3, cw = i & 7;
        dstB[c] = SW128((uint32_t)(i * 16));
        srcB[c] = (uint32_t)r * (D * 2) + cw * 16;
    }
    const char* const xh = (const char*)g_x_h;
    const char* const wh = (const char*)g_w23_h;
    const char* const wl = (const char*)g_w23_l;

    uint32_t Abase[2], Amask[2];
#pragma unroll
    for (int mi = 0; mi < 2; mi++) {
        int m = wid * 32 + (lane & 15) + mi * 16;
        Abase[mi] = (uint32_t)(m * 128);
        Amask[mi] = (uint32_t)((m << 4) & 0x70);
    }
    const uint32_t akb = (uint32_t)((lane >> 4) * 16);
    const uint32_t Bbase = (uint32_t)(lane * 128);
    const uint32_t Bmask = (uint32_t)((lane << 4) & 0x70);

    float acc[2][4][4];
#pragma unroll
    for (int mi = 0; mi < 2; mi++)
#pragma unroll
        for (int ni = 0; ni < 4; ni++)
#pragma unroll
            for (int q = 0; q < 4; q++) acc[mi][ni][q] = 0.f;

    auto load_tile = [&](int kt, uint32_t stage_off) {
        const char* Bb = (kt >= 12) ? wl : wh;
        int ktm = (kt >= 12) ? kt - 12 : kt;
        uint32_t k0b = (uint32_t)(ktm * (BK * 2));
        uint32_t sa = sbase + stage_off;
        uint32_t sb = sa + S_ASTG;
#pragma unroll
        for (int c = 0; c < 8; c++)
            cp_async16(sa + dstA[c], xh + srcA[c] + k0b);
#pragma unroll
        for (int c = 0; c < 2; c++)
            cp_async16(sb + dstB[c], Bb + srcB[c] + k0b);
        asm volatile("cp.async.commit_group;" ::: "memory");
    };

    load_tile(0, 0);
    load_tile(1, S_STAGE);

#pragma unroll 3
    for (int kt = 0; kt < S_KTILES; kt++) {
        const uint32_t soff = (uint32_t)(kt % S_NSTG) * S_STAGE;
        if (kt < S_KTILES - 1)
            asm volatile("cp.async.wait_group 1;" ::: "memory");
        else
            asm volatile("cp.async.wait_group 0;" ::: "memory");
        __syncthreads();

        const int nx = kt + 2;
        if (nx < S_KTILES) load_tile(nx, (uint32_t)(nx % S_NSTG) * S_STAGE);

        const uint32_t sa = sbase + soff;
        const uint32_t sb = sa + S_ASTG;
#pragma unroll
        for (int ks = 0; ks < 4; ks++) {
            const uint32_t kk = (uint32_t)(ks * 32);
            uint32_t b0[4], b1r[4];
            ldmatrix_x4(b0[0], b0[1], b0[2], b0[3],
                        sb + Bbase + ((kk) ^ Bmask));
            ldmatrix_x4(b1r[0], b1r[1], b1r[2], b1r[3],
                        sb + Bbase + ((kk + 16) ^ Bmask));
            uint32_t a[2][4];
#pragma unroll
            for (int mi = 0; mi < 2; mi++)
                ldmatrix_x4(a[mi][0], a[mi][1], a[mi][2], a[mi][3],
                            sa + Abase[mi] + ((kk + akb) ^ Amask[mi]));
#pragma unroll
            for (int mi = 0; mi < 2; mi++)
#pragma unroll
                for (int ni = 0; ni < 4; ni++)
                    mma_f16(acc[mi][ni],
                            a[mi][0], a[mi][1], a[mi][2], a[mi][3],
                            b0[ni], b1r[ni]);
        }
    }

    // s epilogue: cols 0-15 = B-proj, 16-31 = C-proj.
    const int nq = (lane & 3) * 2;
    const float b2a = __ldg(b2 + nq),     b2a1 = __ldg(b2 + nq + 1);
    const float b2b = __ldg(b2 + 8 + nq), b2b1 = __ldg(b2 + 8 + nq + 1);
    const float b3a = __ldg(b3 + nq),     b3a1 = __ldg(b3 + nq + 1);
    const float b3b = __ldg(b3 + 8 + nq), b3b1 = __ldg(b3 + 8 + nq + 1);
#pragma unroll
    for (int mi = 0; mi < 2; mi++) {
        float pa = (acc[mi][0][0] + b2a ) * (acc[mi][2][0] + b3a )
                 + (acc[mi][0][1] + b2a1) * (acc[mi][2][1] + b3a1)
                 + (acc[mi][1][0] + b2b ) * (acc[mi][3][0] + b3b )
                 + (acc[mi][1][1] + b2b1) * (acc[mi][3][1] + b3b1);
        float pb = (acc[mi][0][2] + b2a ) * (acc[mi][2][2] + b3a )
                 + (acc[mi][0][3] + b2a1) * (acc[mi][2][3] + b3a1)
                 + (acc[mi][1][2] + b2b ) * (acc[mi][3][2] + b3b )
                 + (acc[mi][1][3] + b2b1) * (acc[mi][3][3] + b3b1);
        pa += __shfl_xor_sync(0xffffffffu, pa, 1);
        pa += __shfl_xor_sync(0xffffffffu, pa, 2);
        pb += __shfl_xor_sync(0xffffffffu, pb, 1);
        pb += __shfl_xor_sync(0xffffffffu, pb, 2);
        if ((lane & 3) == 0) {
            int ma = row0 + wid * 32 + mi * 16 + (lane >> 2);
            g_s[ma] = pa;
            g_s[ma + 8] = pb;
        }
    }
}

// ---------------------------------------------------------------------------
// Main GEMM: single fp16 term (K=768), mma.sync m16n8k16, cp.async 3-stage.
// CTA 128x64, 8 warps (warp grid 4m x 2n, warp tile 32x32), 3 CTAs/SM.
// Fused epilogue: y = x_h * softplus(acc + b1) * s[m]   (x_h fp16, L2-hot).
// ---------------------------------------------------------------------------
__global__ void __launch_bounds__(256, 3) s6_mma_gemm(
    const float* __restrict__ b1, float* __restrict__ y)
{
    extern __shared__ __align__(1024) char smem[];
    const uint32_t sbase = smem_u32(smem);
    const int tid = threadIdx.x;
    const int wid = tid >> 5, lane = tid & 31;
    const int warp_m = wid & 3;        // 4 m-blocks of 32
    const int warp_n = wid >> 2;       // 2 n-blocks of 32
    const int row0 = blockIdx.y * BM;
    const int col0 = blockIdx.x * BN;

    uint32_t dstA[4], srcA[4], dstB[2], srcB[2];
#pragma unroll
    for (int c = 0; c < 4; c++) {
        int i = c * 256 + tid;
        int r = i >> 3, cw = i & 7;
        dstA[c] = SW128((uint32_t)(i * 16));
        srcA[c] = (uint32_t)(row0 + r) * (D * 2) + cw * 16;
    }
#pragma unroll
    for (int c = 0; c < 2; c++) {
        int i = c * 256 + tid;
        int r = i >> 3, cw = i & 7;
        dstB[c] = SW128((uint32_t)(i * 16));
        srcB[c] = (uint32_t)(col0 + r) * (D * 2) + cw * 16;
    }
    const char* const xh = (const char*)g_x_h;
    const char* const wh = (const char*)g_wt_h;

    uint32_t Abase[2], Amask[2];
#pragma unroll
    for (int mi = 0; mi < 2; mi++) {
        int m = warp_m * 32 + (lane & 15) + mi * 16;
        Abase[mi] = (uint32_t)(m * 128);
        Amask[mi] = (uint32_t)((m << 4) & 0x70);
    }
    const uint32_t akb = (uint32_t)((lane >> 4) * 16);
    const int bn = warp_n * 32 + lane;
    const uint32_t Bbase = (uint32_t)(bn * 128);
    const uint32_t Bmask = (uint32_t)((bn << 4) & 0x70);

    float acc[2][4][4];
#pragma unroll
    for (int mi = 0; mi < 2; mi++)
#pragma unroll
        for (int ni = 0; ni < 4; ni++)
#pragma unroll
            for (int q = 0; q < 4; q++) acc[mi][ni][q] = 0.f;

    auto load_tile = [&](int kt, uint32_t stage_off) {
        uint32_t k0b = (uint32_t)(kt * (BK * 2));
        uint32_t sa = sbase + stage_off;
        uint32_t sb = sa + ASTAGE;
#pragma unroll
        for (int c = 0; c < 4; c++)
            cp_async16(sa + dstA[c], xh + srcA[c] + k0b);
#pragma unroll
        for (int c = 0; c < 2; c++)
            cp_async16(sb + dstB[c], wh + srcB[c] + k0b);
        asm volatile("cp.async.commit_group;" ::: "memory");
    };

    load_tile(0, 0);
    load_tile(1, STAGE_BYTES);

#pragma unroll 3
    for (int kt = 0; kt < KTILES; kt++) {
        const uint32_t soff = (uint32_t)(kt % NSTG) * STAGE_BYTES;
        if (kt < KTILES - 1)
            asm volatile("cp.async.wait_group 1;" ::: "memory");
        else
            asm volatile("cp.async.wait_group 0;" ::: "memory");
        __syncthreads();

        const int nx = kt + 2;
        if (nx < KTILES) load_tile(nx, (uint32_t)(nx % NSTG) * STAGE_BYTES);

        const uint32_t sa = sbase + soff;
        const uint32_t sb = sa + ASTAGE;
#pragma unroll
        for (int ks = 0; ks < 4; ks++) {
            const uint32_t kk = (uint32_t)(ks * 32);
            uint32_t b0[4], b1r[4];
            ldmatrix_x4(b0[0], b0[1], b0[2], b0[3],
                        sb + Bbase + ((kk) ^ Bmask));
            ldmatrix_x4(b1r[0], b1r[1], b1r[2], b1r[3],
                        sb + Bbase + ((kk + 16) ^ Bmask));
            uint32_t a[2][4];
#pragma unroll
            for (int mi = 0; mi < 2; mi++)
                ldmatrix_x4(a[mi][0], a[mi][1], a[mi][2], a[mi][3],
                            sa + Abase[mi] + ((kk + akb) ^ Amask[mi]));
#pragma unroll
            for (int mi = 0; mi < 2; mi++)
#pragma unroll
                for (int ni = 0; ni < 4; ni++)
                    mma_f16(acc[mi][ni],
                            a[mi][0], a[mi][1], a[mi][2], a[mi][3],
                            b0[ni], b1r[ni]);
        }
    }

    // Fused epilogue (x read as fp16 from g_x_h — L2-hot, half the bytes)
    const int mbase = row0 + warp_m * 32;
    const int nbase = col0 + warp_n * 32;
#pragma unroll
    for (int mi = 0; mi < 2; mi++) {
        const int ma = mbase + mi * 16 + (lane >> 2);
        const int mb = ma + 8;
        const float s_a = g_s[ma];
        const float s_b = g_s[mb];
#pragma unroll
        for (int ni = 0; ni < 4; ni++) {
            const int n = nbase + ni * 8 + (lane & 3) * 2;
            float2 bb = *(const float2*)(b1 + n);
            __half2 xah = *(const __half2*)(g_x_h + (size_t)ma * D + n);
            __half2 xbh = *(const __half2*)(g_x_h + (size_t)mb * D + n);
            float2 xa = __half22float2(xah);
            float2 xb = __half22float2(xbh);
            float2 oa, ob;
            oa.x = xa.x * softplus_f(acc[mi][ni][0] + bb.x) * s_a;
            oa.y = xa.y * softplus_f(acc[mi][ni][1] + bb.y) * s_a;
            ob.x = xb.x * softplus_f(acc[mi][ni][2] + bb.x) * s_b;
            ob.y = xb.y * softplus_f(acc[mi][ni][3] + bb.y) * s_b;
            *(float2*)(y + (size_t)ma * D + n) = oa;
            *(float2*)(y + (size_t)mb * D + n) = ob;
        }
    }
}

// ---------------------------------------------------------------------------
// Launch. Inputs: x, W1, b1, W2, b2, W3, b3, A (A unused since h0 = 0).
// ---------------------------------------------------------------------------
extern "C" void kernel_launch(void* const* d_in, const int* in_sizes, int n_in,
                              void* d_out, int out_size)
{
    const float* x  = (const float*)d_in[0];
    const float* W1 = (const float*)d_in[1];
    const float* b1 = (const float*)d_in[2];
    const float* W2 = (const float*)d_in[3];
    const float* b2 = (const float*)d_in[4];
    const float* W3 = (const float*)d_in[5];
    const float* b3 = (const float*)d_in[6];
    float* y = (float*)d_out;

    static bool attr_set = false;
    if (!attr_set) {
        cudaFuncSetAttribute(s6_mma_gemm,
                             cudaFuncAttributeMaxDynamicSharedMemorySize, GEMM_SMEM);
        cudaFuncSetAttribute(k_s_mma,
                             cudaFuncAttributeMaxDynamicSharedMemorySize, S_SMEM);
        attr_set = true;
    }

    k_conv<<<CONV_XBLK + WT_TILES + W23_BLKS, 256>>>(x, W1, W2, W3);
    k_s_mma<<<M_TOTAL / SBM, 128, S_SMEM>>>(b2, b3);

    dim3 grid(D / BN, M_TOTAL / BM);   // (12, 64) = 768 CTAs
    s6_mma_gemm<<<grid, 256, GEMM_SMEM>>>(b1, y);
}